// round 3
// baseline (speedup 1.0000x reference)
#include <cuda_runtime.h>
#include <math.h>

#define VOCAB   50257
#define EMBED   128
#define HIDDEN  128
#define NCLASS  4
#define BB      256
#define TT      512
#define NTOK    (BB * TT)          // 131072

// x_proj scratch [t][b][h] : 64MB device global (no runtime alloc)
__device__ float g_xp[TT * BB * HIDDEN];

// ---------------------------------------------------------------- helpers
__device__ __forceinline__ unsigned smem_u32(const void* p) {
    return (unsigned)__cvta_generic_to_shared(p);
}
__device__ __forceinline__ void cp_async4(void* dst, const void* src) {
    asm volatile("cp.async.ca.shared.global [%0], [%1], 4;"
                 :: "r"(smem_u32(dst)), "l"(src));
}
__device__ __forceinline__ void cp_commit() {
    asm volatile("cp.async.commit_group;");
}
__device__ __forceinline__ void cp_wait1() {
    asm volatile("cp.async.wait_group 1;");
}
__device__ __forceinline__ void cp_wait0() {
    asm volatile("cp.async.wait_group 0;");
}
// packed dual fp32 FMA (sm_103a f32x2 pipe)
__device__ __forceinline__ unsigned long long
fma2(unsigned long long a, unsigned long long b, unsigned long long c) {
    unsigned long long d;
    asm("fma.rn.f32x2 %0, %1, %2, %3;" : "=l"(d) : "l"(a), "l"(b), "l"(c));
    return d;
}
__device__ __forceinline__ float2 unpack2(unsigned long long v) {
    float2 r;
    asm("mov.b64 {%0, %1}, %2;" : "=f"(r.x), "=f"(r.y) : "l"(v));
    return r;
}
__device__ __forceinline__ float fast_tanh(float x) {
    x = fminf(fmaxf(x, -15.0f), 15.0f);
    float e = __expf(2.0f * x);
    return 1.0f - __fdividef(2.0f, e + 1.0f);
}

// 128-float dot against register weights, with software-pipelined
// double-buffered shared loads (batches of 4 ulonglong2 = 16 floats).
// 'src' must be 16B-aligned shared memory (128 floats).
__device__ __forceinline__ float dot128_pipelined(
    const ulonglong2* __restrict__ src, const unsigned long long* __restrict__ w2)
{
    ulonglong2 bufA[4], bufB[4];
    #pragma unroll
    for (int i = 0; i < 4; ++i) bufA[i] = src[i];

    unsigned long long acc0 = 0, acc1 = 0, acc2 = 0, acc3 = 0;
    #pragma unroll
    for (int bt = 0; bt < 8; ++bt) {
        const ulonglong2* cur = (bt & 1) ? bufB : bufA;
        ulonglong2*       nxt = (bt & 1) ? bufA : bufB;
        if (bt < 7) {
            #pragma unroll
            for (int i = 0; i < 4; ++i) nxt[i] = src[(bt + 1) * 4 + i];
        }
        #pragma unroll
        for (int i = 0; i < 4; ++i) {
            const int k4 = bt * 4 + i;
            if (k4 & 1) {
                acc2 = fma2(w2[k4 * 2],     cur[i].x, acc2);
                acc3 = fma2(w2[k4 * 2 + 1], cur[i].y, acc3);
            } else {
                acc0 = fma2(w2[k4 * 2],     cur[i].x, acc0);
                acc1 = fma2(w2[k4 * 2 + 1], cur[i].y, acc1);
            }
        }
    }
    float2 u0 = unpack2(acc0), u1 = unpack2(acc1);
    float2 u2 = unpack2(acc2), u3 = unpack2(acc3);
    return ((u0.x + u0.y) + (u1.x + u1.y)) + ((u2.x + u2.y) + (u3.x + u3.y));
}

// ---------------------------------------------------------------------------
// Kernel 1: x_proj[t,b,:] = emb[x[b,t],:] @ W_ih^T + (b_ih + b_hh)
// 148 CTAs x 256 threads. Thread owns one output (out = tid&127) with the full
// weight row in registers (64 x f32x2). Warps 0-3 handle even token slots,
// warps 4-7 odd slots. Embeddings staged 16 tokens at a time via cp.async
// (double buffered); activation reads are broadcast LDS.128, pipelined.
// ---------------------------------------------------------------------------
#define XP_GRID  148
#define XP_TPC   886            // tokens per CTA (148*886 >= 131072)
#define XP_CH    16             // tokens per staged chunk
#define XP_NC    ((XP_TPC + XP_CH - 1) / XP_CH)   // 56

__global__ void __launch_bounds__(256, 1) xproj_kernel(
    const int* __restrict__ x, const float* __restrict__ emb,
    const float* __restrict__ W_ih, const float* __restrict__ b_ih,
    const float* __restrict__ b_hh)
{
    extern __shared__ float sh[];
    int*   s_ids = (int*)sh;                 // 896 ids
    float* s_buf = sh + 896;                 // 2 x (16*128) floats = 16KB

    const int tid  = threadIdx.x;
    const int out  = tid & 127;
    const int half = tid >> 7;               // token-slot subgroup
    const int r0   = blockIdx.x * XP_TPC;

    // stage token ids (pad with 0 -> emb pad row is zero, harmless)
    for (int i = tid; i < 896; i += 256) {
        int r = r0 + i;
        s_ids[i] = (i < XP_TPC && r < NTOK) ? x[r] : 0;
    }

    // stage W_ih -> per-thread registers via 4 coalesced shared passes
    unsigned long long w2[64];
    for (int p = 0; p < 4; ++p) {
        for (int i = tid; i < 32 * 128; i += 256)
            s_buf[i] = W_ih[p * 32 * 128 + i];
        __syncthreads();
        if ((out >> 5) == p) {
            const unsigned long long* row =
                (const unsigned long long*)(s_buf + (out & 31) * 128);
            #pragma unroll
            for (int k = 0; k < 64; ++k) w2[k] = row[k];
        }
        __syncthreads();
    }
    const float bias = b_ih[out] + b_hh[out];

    // prologue: stage chunk 0
    {
        float* dst = s_buf;
        #pragma unroll
        for (int j = 0; j < 8; ++j) {
            int slot = j * 2 + half;
            int id = s_ids[slot];
            cp_async4(dst + slot * 128 + out, emb + (size_t)id * EMBED + out);
        }
        cp_commit();
    }

    for (int c = 0; c < XP_NC; ++c) {
        // stage chunk c+1 into the other buffer
        if (c + 1 < XP_NC) {
            float* dst = s_buf + ((c + 1) & 1) * (XP_CH * 128);
            #pragma unroll
            for (int j = 0; j < 8; ++j) {
                int slot = j * 2 + half;
                int id = s_ids[(c + 1) * XP_CH + slot];
                cp_async4(dst + slot * 128 + out, emb + (size_t)id * EMBED + out);
            }
            cp_commit();
            cp_wait1();
        } else {
            cp_wait0();
        }
        __syncthreads();

        const float* buf = s_buf + (c & 1) * (XP_CH * 128);
        #pragma unroll 2
        for (int j = 0; j < 8; ++j) {
            int slot = half * 8 + j;
            int i_tok = c * XP_CH + slot;
            int r = r0 + i_tok;
            if (i_tok < XP_TPC && r < NTOK) {
                float s = dot128_pipelined(
                    (const ulonglong2*)(buf + slot * 128), w2) + bias;
                int b = r >> 9, t = r & (TT - 1);
                g_xp[((size_t)t * BB + b) * HIDDEN + out] = s;
            }
        }
        __syncthreads();
    }
}

// ---------------------------------------------------------------------------
// Kernel 2: recurrence. 128 CTAs x 256 threads (1 CTA/SM). CTA owns rows
// (2*blk, 2*blk+1); thread owns one (row, output): row = tid>>7, out = tid&127.
// W_hh register-resident (64 f32x2/thread). h double-buffered in shared ->
// ONE __syncthreads per step. xp prefetched one step ahead. Shared h loads
// software-pipelined against the fma2 stream.
// ---------------------------------------------------------------------------
__global__ void __launch_bounds__(256, 1) rnn_kernel(
    const float* __restrict__ h0, const float* __restrict__ W_hh,
    float* __restrict__ out_hidden)
{
    extern __shared__ float sh[];
    float* s_h   = sh;            // [2 bufs][2 rows][128]
    float* s_stg = sh + 512;      // 4096 floats staging for W

    const int tid = threadIdx.x;
    const int out = tid & 127;
    const int row = tid >> 7;
    const int b   = blockIdx.x * 2 + row;

    // stage W_hh -> registers (4 coalesced passes through shared)
    unsigned long long w2[64];
    for (int p = 0; p < 4; ++p) {
        for (int i = tid; i < 32 * 128; i += 256)
            s_stg[i] = W_hh[p * 32 * 128 + i];
        __syncthreads();
        if ((out >> 5) == p) {
            const unsigned long long* wrow =
                (const unsigned long long*)(s_stg + (out & 31) * 128);
            #pragma unroll
            for (int k = 0; k < 64; ++k) w2[k] = wrow[k];
        }
        __syncthreads();
    }

    // init h buffer 0
    s_h[row * 128 + out] = h0[(size_t)b * HIDDEN + out];
    __syncthreads();

    const float* xp_me = g_xp + (size_t)b * HIDDEN + out;
    float xv_cur = __ldg(xp_me);
    float h = 0.0f;

    for (int t = 0; t < TT; ++t) {
        float xv_next = (t + 1 < TT)
            ? __ldg(xp_me + (size_t)(t + 1) * (BB * HIDDEN)) : 0.0f;

        const ulonglong2* h4 =
            (const ulonglong2*)(s_h + (t & 1) * 256 + row * 128);
        float s = dot128_pipelined(h4, w2) + xv_cur;
        h = fast_tanh(s);
        s_h[((t + 1) & 1) * 256 + row * 128 + out] = h;
        xv_cur = xv_next;
        __syncthreads();
    }

    out_hidden[(size_t)b * HIDDEN + out] = h;
}

// ---------------------------------------------------------------------------
// Kernel 3: MLP head. One CTA per batch row.
// ---------------------------------------------------------------------------
__global__ void __launch_bounds__(256) head_kernel(
    const float* __restrict__ hidden, const float* __restrict__ W1,
    const float* __restrict__ b1, const float* __restrict__ W2,
    const float* __restrict__ b2, float* __restrict__ logits)
{
    __shared__ float shH[HIDDEN];
    __shared__ float shM[2 * HIDDEN];
    const int b = blockIdx.x, tid = threadIdx.x;
    if (tid < HIDDEN) shH[tid] = hidden[(size_t)b * HIDDEN + tid];
    __syncthreads();

    float acc = b1[tid];
    const float4* w4 = (const float4*)(W1 + (size_t)tid * HIDDEN);
    const float4* h4 = (const float4*)shH;
    #pragma unroll 8
    for (int k4 = 0; k4 < 32; ++k4) {
        float4 w = w4[k4];
        float4 h = h4[k4];
        acc = fmaf(w.x, h.x, acc);
        acc = fmaf(w.y, h.y, acc);
        acc = fmaf(w.z, h.z, acc);
        acc = fmaf(w.w, h.w, acc);
    }
    shM[tid] = fmaxf(acc, 0.0f);
    __syncthreads();

    if (tid < NCLASS) {
        float a = b2[tid];
        const float* w2 = W2 + (size_t)tid * (2 * HIDDEN);
        #pragma unroll 8
        for (int k = 0; k < 2 * HIDDEN; ++k)
            a = fmaf(shM[k], w2[k], a);
        logits[(size_t)b * NCLASS + tid] = a;
    }
}

// ---------------------------------------------------------------------------
extern "C" void kernel_launch(void* const* d_in, const int* in_sizes, int n_in,
                              void* d_out, int out_size)
{
    const int*   x    = (const int*)  d_in[0];
    const float* h0   = (const float*)d_in[1];
    const float* emb  = (const float*)d_in[2];
    const float* W_ih = (const float*)d_in[3];
    const float* W_hh = (const float*)d_in[4];
    const float* b_ih = (const float*)d_in[5];
    const float* b_hh = (const float*)d_in[6];
    const float* W1   = (const float*)d_in[7];
    const float* b1   = (const float*)d_in[8];
    const float* W2   = (const float*)d_in[9];
    const float* b2   = (const float*)d_in[10];

    float* out    = (float*)d_out;
    float* logits = out;                 // [256*4]
    float* hidden = out + BB * NCLASS;   // [256*128]

    const int smem1 = (896 + 2 * XP_CH * 128) * sizeof(float);  // ~20KB
    const int smem2 = (512 + 32 * 128) * sizeof(float);         // ~18.5KB

    xproj_kernel<<<XP_GRID, 256, smem1>>>(x, emb, W_ih, b_ih, b_hh);
    rnn_kernel<<<BB / 2, 256, smem2>>>(h0, W_hh, hidden);
    head_kernel<<<BB, 256>>>(hidden, W1, b1, W2, b2, logits);
}